// round 16
// baseline (speedup 1.0000x reference)
#include <cuda_runtime.h>

#define BINS 10
#define TPB  256
#define BPSM 8
#define GRID (152 * BPSM)   // 1216 blocks: 8/SM -> 64 warps/SM

// Contention-free publication: each block owns 10 float2 slots.
// (allocation-free __device__ globals; overwritten fully each run)
__device__ float2       g_part[GRID * BINS];
__device__ unsigned int g_done;

__device__ __forceinline__ float rcp_fast(float x) { float r; asm("rcp.approx.f32 %0, %1;" : "=f"(r) : "f"(x)); return r; }
__device__ __forceinline__ float lg2_fast(float x) { float r; asm("lg2.approx.f32 %0, %1;" : "=f"(r) : "f"(x)); return r; }
__device__ __forceinline__ float ex2_fast(float x) { float r; asm("ex2.approx.f32 %0, %1;" : "=f"(r) : "f"(x)); return r; }

// s = x ^ mask (mask = target-match << 31);  |s| = |x|
//   e = exp(-|x|);  d = 1+e;  u = 9.9999*rcp(d)
//   us = (s>=0) ? u : 9.9999-u;  bin = trunc(us) in [0,9]
//   bce = (s>=0 ? |x| : 0) + ln2*lg2(d)
__device__ __forceinline__ void ghm_elem(float x, unsigned mask, float2 (*hist)[TPB], int tid)
{
    int   sx = __float_as_int(x) ^ (int)mask;
    float ax = fabsf(x);
    float e  = ex2_fast(ax * -1.4426950408889634f);
    float d  = 1.0f + e;
    float u  = rcp_fast(d) * 9.9999f;
    bool pos = (sx >= 0);
    float us = pos ? u : (9.9999f - u);
    int  bin = (int)us;
    float m  = pos ? ax : 0.0f;
    float bce = fmaf(lg2_fast(d), 0.69314718055994531f, m);
    float2 h = hist[bin][tid];
    h.x += 1.0f;
    h.y += bce;
    hist[bin][tid] = h;
}

__global__ void __launch_bounds__(TPB, BPSM)
ghm_fused(const float4* __restrict__ x4,
          const int2*   __restrict__ t2,
          int npairs, int nrows,
          const float* __restrict__ xs,
          const int*   __restrict__ ts,
          float* __restrict__ out)
{
    // Single privatized histogram: hist[bin][tid], float2 = (count, bce_sum).
    // Stride 8B -> bank = tid (mod 32): conflict-free for any bin mix.
    __shared__ float2 hist[BINS][TPB];
    __shared__ int    s_last;
    const int tid = threadIdx.x;
#pragma unroll
    for (int b = 0; b < BINS; b++) hist[b][tid] = make_float2(0.0f, 0.0f);
    __syncthreads();

    // Main loop (R13/R14's proven-best config): 2 rows (4 elements)/iter,
    // latency hiding from 64 warps/SM.
    const int stride = GRID * TPB;
    for (int i = blockIdx.x * TPB + tid; i < npairs; i += stride) {
        float4 xv = x4[i];   // rows 2i (x,y) and 2i+1 (z,w)
        int2   tv = t2[i];

        unsigned m1a = ((unsigned)tv.x) << 31, m0a = m1a ^ 0x80000000u;
        unsigned m1b = ((unsigned)tv.y) << 31, m0b = m1b ^ 0x80000000u;

        ghm_elem(xv.x, m0a, hist, tid);
        ghm_elem(xv.y, m1a, hist, tid);
        ghm_elem(xv.z, m0b, hist, tid);
        ghm_elem(xv.w, m1b, hist, tid);
    }

    // Tail row (nrows odd): thread 0 of block 0 folds it into its own smem
    // column (column 0 belongs to thread 0 — no race before the barrier).
    if (blockIdx.x == 0 && tid == 0 && (nrows & 1)) {
        int rowi = nrows - 1;
        int t = ts[rowi];
        for (int c = 0; c < 2; c++) {
            float x = xs[rowi * 2 + c];
            unsigned mask = ((t == c) ? 0x80000000u : 0u);
            int   sx = __float_as_int(x) ^ (int)mask;
            float ax = fabsf(x);
            float e  = ex2_fast(ax * -1.4426950408889634f);
            float d  = 1.0f + e;
            float u  = rcp_fast(d) * 9.9999f;
            bool pos = (sx >= 0);
            float us = pos ? u : (9.9999f - u);
            int  bin = (int)us;
            float m  = pos ? ax : 0.0f;
            float bce = fmaf(lg2_fast(d), 0.69314718055994531f, m);
            float2 h = hist[bin][0];
            h.x += 1.0f; h.y += bce;
            hist[bin][0] = h;
        }
    }
    __syncthreads();

    // Tree-reduce 256 columns x 10 bins -> block totals in hist[b][0].
    for (int off = TPB / 2; off > 0; off >>= 1) {
        if (tid < off) {
#pragma unroll
            for (int b = 0; b < BINS; b++) {
                float2 a = hist[b][tid];
                float2 c = hist[b][tid + off];
                hist[b][tid] = make_float2(a.x + c.x, a.y + c.y);
            }
        }
        __syncthreads();
    }

    // CONTENTION-FREE publish: 10 STG.64 to this block's own slots
    // (no atomics -> the fence waits only on independent store acks).
    if (tid < BINS)
        g_part[blockIdx.x * BINS + tid] = hist[tid][0];
    __threadfence();   // release: publish stores before the ticket
    __syncthreads();

    // Ticket: last block to arrive runs the gather + finalize.
    if (tid == 0) {
        unsigned old = atomicAdd(&g_done, 1u);
        s_last = (old == GRID - 1) ? 1 : 0;
    }
    __syncthreads();

    if (s_last) {
        __threadfence();   // acquire: all published parts now visible

        // Re-zero our hist, then gather 1216x10 float2 from L2 (independent
        // __ldcg loads, fully overlapped) back into the conflict-free layout.
#pragma unroll
        for (int b = 0; b < BINS; b++) hist[b][tid] = make_float2(0.0f, 0.0f);
        __syncthreads();

        for (int j = tid; j < GRID * BINS; j += TPB) {
            float2 v = __ldcg(&g_part[j]);
            int bin = j - (j / BINS) * BINS;   // j % 10
            float2 h = hist[bin][tid];
            h.x += v.x; h.y += v.y;
            hist[bin][tid] = h;
        }
        __syncthreads();

        // Tree-reduce the gathered partials.
        for (int off = TPB / 2; off > 0; off >>= 1) {
            if (tid < off) {
#pragma unroll
                for (int b = 0; b < BINS; b++) {
                    float2 a = hist[b][tid];
                    float2 c = hist[b][tid + off];
                    hist[b][tid] = make_float2(a.x + c.x, a.y + c.y);
                }
            }
            __syncthreads();
        }

        // Parallel finalize (warp 0): counts are exact in f32 (N = 2^24).
        if (tid < 32) {
            double cnt = 0.0, sum = 0.0;
            if (tid < BINS) {
                float2 tot = hist[tid][0];
                cnt = (double)tot.x;
                sum = (double)tot.y;
            }
            unsigned ball = __ballot_sync(0xffffffffu, (tid < BINS) && (cnt > 0.0));
            double nonempty = (double)__popc(ball);

            double term = 0.0;
            if (tid < BINS) {
                double gd = cnt * nonempty;
                if (gd < 1e-4) gd = 1e-4;
                term = sum / gd;
            }
#pragma unroll
            for (int off = 16; off > 0; off >>= 1)
                term += __shfl_down_sync(0xffffffffu, term, off);

            if (tid == 0) {
                out[0] = (float)term;
                g_done = 0u;   // reset for next graph replay (kernel-end fence)
            }
        }
    }
}

extern "C" void kernel_launch(void* const* d_in, const int* in_sizes, int n_in,
                              void* d_out, int out_size)
{
    // x: [B,2] float32 (2B elems), target: [B] int32 (B elems) — identify by count.
    const float* x;
    const int*   t;
    int nrows;
    if (in_sizes[0] >= 2 * in_sizes[1]) {
        x = (const float*)d_in[0];
        t = (const int*)d_in[1];
        nrows = in_sizes[1];
    } else {
        x = (const float*)d_in[1];
        t = (const int*)d_in[0];
        nrows = in_sizes[0];
    }
    int npairs = nrows >> 1;   // 2 rows (4 elements) per iteration

    ghm_fused<<<GRID, TPB>>>((const float4*)x, (const int2*)t, npairs, nrows,
                             x, t, (float*)d_out);
}

// round 17
// speedup vs baseline: 1.2703x; 1.2703x over previous
#include <cuda_runtime.h>

#define BINS 10
#define TPB  256
#define BPSM 8
#define GRID (152 * BPSM)   // 8 blocks/SM -> 64 warps/SM

// Global scratch (allocation-free __device__ globals, zero-init at load;
// the finalize kernel re-zeros them so graph replays stay deterministic).
__device__ double g_cnt[BINS];
__device__ double g_sum[BINS];

__device__ __forceinline__ float rcp_fast(float x) { float r; asm("rcp.approx.f32 %0, %1;" : "=f"(r) : "f"(x)); return r; }
__device__ __forceinline__ float lg2_fast(float x) { float r; asm("lg2.approx.f32 %0, %1;" : "=f"(r) : "f"(x)); return r; }
__device__ __forceinline__ float ex2_fast(float x) { float r; asm("ex2.approx.f32 %0, %1;" : "=f"(r) : "f"(x)); return r; }

// s = x ^ mask (mask = target-match << 31);  |s| = |x|
//   e = exp(-|x|);  d = 1+e;  u = 9.9999*rcp(d)
//   us = (s>=0) ? u : 9.9999-u;  bin = trunc(us) in [0,9]
//   bce = (s>=0 ? |x| : 0) + ln2*lg2(d)
__device__ __forceinline__ void ghm_elem(float x, unsigned mask, float2 (*hist)[TPB], int tid)
{
    int   sx = __float_as_int(x) ^ (int)mask;
    float ax = fabsf(x);
    float e  = ex2_fast(ax * -1.4426950408889634f);
    float d  = 1.0f + e;
    float u  = rcp_fast(d) * 9.9999f;
    bool pos = (sx >= 0);
    float us = pos ? u : (9.9999f - u);
    int  bin = (int)us;
    float m  = pos ? ax : 0.0f;
    float bce = fmaf(lg2_fast(d), 0.69314718055994531f, m);
    float2 h = hist[bin][tid];
    h.x += 1.0f;
    h.y += bce;
    hist[bin][tid] = h;
}

// MAIN kernel: identical to R14's measured-best.
__global__ void __launch_bounds__(TPB, BPSM)
ghm_main(const float4* __restrict__ x4,
         const int2*   __restrict__ t2,
         int npairs, int nrows,
         const float* __restrict__ xs,
         const int*   __restrict__ ts)
{
    // Single privatized histogram: hist[bin][tid], float2 = (count, bce_sum).
    // Stride 8B -> bank = tid (mod 32): conflict-free for any bin mix.
    __shared__ float2 hist[BINS][TPB];
    const int tid = threadIdx.x;
#pragma unroll
    for (int b = 0; b < BINS; b++) hist[b][tid] = make_float2(0.0f, 0.0f);
    __syncthreads();

    const int stride = GRID * TPB;
    for (int i = blockIdx.x * TPB + tid; i < npairs; i += stride) {
        float4 xv = x4[i];   // rows 2i (x,y) and 2i+1 (z,w)
        int2   tv = t2[i];

        unsigned m1a = ((unsigned)tv.x) << 31, m0a = m1a ^ 0x80000000u;
        unsigned m1b = ((unsigned)tv.y) << 31, m0b = m1b ^ 0x80000000u;

        ghm_elem(xv.x, m0a, hist, tid);
        ghm_elem(xv.y, m1a, hist, tid);
        ghm_elem(xv.z, m0b, hist, tid);
        ghm_elem(xv.w, m1b, hist, tid);
    }

    // Tail row (nrows odd): one thread, direct double atomics.
    if (blockIdx.x == 0 && tid == 0 && (nrows & 1)) {
        int rowi = nrows - 1;
        int t = ts[rowi];
        for (int c = 0; c < 2; c++) {
            float x = xs[rowi * 2 + c];
            unsigned mask = ((t == c) ? 0x80000000u : 0u);
            int   sx = __float_as_int(x) ^ (int)mask;
            float ax = fabsf(x);
            float e  = ex2_fast(ax * -1.4426950408889634f);
            float d  = 1.0f + e;
            float u  = rcp_fast(d) * 9.9999f;
            bool pos = (sx >= 0);
            float us = pos ? u : (9.9999f - u);
            int  bin = (int)us;
            float m  = pos ? ax : 0.0f;
            float bce = fmaf(lg2_fast(d), 0.69314718055994531f, m);
            atomicAdd(&g_cnt[bin], 1.0);
            atomicAdd(&g_sum[bin], (double)bce);
        }
    }
    __syncthreads();

    // Tree-reduce 256 columns x 10 bins, then one atomic pair per bin.
    for (int off = TPB / 2; off > 0; off >>= 1) {
        if (tid < off) {
#pragma unroll
            for (int b = 0; b < BINS; b++) {
                float2 a = hist[b][tid];
                float2 c = hist[b][tid + off];
                hist[b][tid] = make_float2(a.x + c.x, a.y + c.y);
            }
        }
        __syncthreads();
    }

    if (tid < BINS) {
        atomicAdd(&g_cnt[tid], (double)hist[tid][0].x);
        atomicAdd(&g_sum[tid], (double)hist[tid][0].y);
    }
}

// FINALIZE kernel with PDL: launched with ProgrammaticStreamSerialization so
// its launch latency overlaps ghm_main's execution; griddepcontrol.wait
// blocks until ghm_main completes (all its atomics then globally visible).
__global__ void ghm_final(float* __restrict__ out)
{
    asm volatile("griddepcontrol.wait;" ::: "memory");

    const int tid = threadIdx.x;
    double cnt = 0.0, sum = 0.0;
    if (tid < BINS) {                  // 20 parallel loads, one exposure
        cnt = g_cnt[tid];
        sum = g_sum[tid];
    }

    unsigned ball = __ballot_sync(0xffffffffu, (tid < BINS) && (cnt > 0.0));
    double nonempty = (double)__popc(ball);

    double term = 0.0;
    if (tid < BINS) {
        double gd = cnt * nonempty;
        if (gd < 1e-4) gd = 1e-4;
        term = sum / gd;               // parallel DP divides
    }

    // Warp reduction (sum of 10 terms; others contribute 0).
#pragma unroll
    for (int off = 16; off > 0; off >>= 1)
        term += __shfl_down_sync(0xffffffffu, term, off);

    if (tid == 0) out[0] = (float)term;

    // Reset for the next graph replay (parallel).
    if (tid < BINS) {
        g_cnt[tid] = 0.0;
        g_sum[tid] = 0.0;
    }
}

extern "C" void kernel_launch(void* const* d_in, const int* in_sizes, int n_in,
                              void* d_out, int out_size)
{
    // x: [B,2] float32 (2B elems), target: [B] int32 (B elems) — identify by count.
    const float* x;
    const int*   t;
    int nrows;
    if (in_sizes[0] >= 2 * in_sizes[1]) {
        x = (const float*)d_in[0];
        t = (const int*)d_in[1];
        nrows = in_sizes[1];
    } else {
        x = (const float*)d_in[1];
        t = (const int*)d_in[0];
        nrows = in_sizes[0];
    }
    int npairs = nrows >> 1;   // 2 rows (4 elements) per iteration

    ghm_main<<<GRID, TPB>>>((const float4*)x, (const int2*)t, npairs, nrows, x, t);

    // PDL launch of the finalize: overlaps its launch overhead with ghm_main.
    cudaLaunchConfig_t cfg = {};
    cfg.gridDim  = dim3(1, 1, 1);
    cfg.blockDim = dim3(32, 1, 1);
    cudaLaunchAttribute attrs[1];
    attrs[0].id = cudaLaunchAttributeProgrammaticStreamSerialization;
    attrs[0].val.programmaticStreamSerializationAllowed = 1;
    cfg.attrs    = attrs;
    cfg.numAttrs = 1;
    cudaLaunchKernelEx(&cfg, ghm_final, (float*)d_out);
}